// round 4
// baseline (speedup 1.0000x reference)
#include <cuda_runtime.h>
#include <cuda_bf16.h>
#include <cstdint>

// ---------------------------------------------------------------------------
// Banded causal attention (Longformer w=128, window 256, D=64) on mma.sync
// bf16 HMMA, 3-product fp32 emulation. CTA = 128 q-rows, 16 warps (512 thr).
// Warp pair (2w, 2w+1) co-owns 16 q-rows, splitting n-tiles by parity.
// ---------------------------------------------------------------------------

#define QP 144u
#define KP 144u
#define VP 144u
#define QHI 0u
#define QLO 18432u
#define KHI 36864u
#define KLO 73728u
#define VHI 110592u
#define VLO 147456u
#define AMS 184320u
#define REDM 185344u
#define REDS 186368u
#define OEX KHI            // O-exchange aliases dead K region after QK
#define SMEM_TOTAL 187392

static __device__ __forceinline__ uint32_t smem_u32(const void* p) {
    uint32_t a;
    asm("{ .reg .u64 t; cvta.to.shared.u64 t, %1; cvt.u32.u64 %0, t; }"
        : "=r"(a) : "l"(p));
    return a;
}
// pack two f32 -> bf16x2 (first arg lands in low half)
static __device__ __forceinline__ uint32_t packb(float lo, float hi) {
    uint32_t r;
    asm("cvt.rn.bf16x2.f32 %0, %1, %2;" : "=r"(r) : "f"(hi), "f"(lo));
    return r;
}
static __device__ __forceinline__ void ldsm4(uint32_t r[4], uint32_t a) {
    asm volatile("ldmatrix.sync.aligned.m8n8.x4.shared.b16 {%0,%1,%2,%3}, [%4];"
                 : "=r"(r[0]), "=r"(r[1]), "=r"(r[2]), "=r"(r[3]) : "r"(a));
}
static __device__ __forceinline__ void ldsm4t(uint32_t r[4], uint32_t a) {
    asm volatile("ldmatrix.sync.aligned.m8n8.x4.trans.shared.b16 {%0,%1,%2,%3}, [%4];"
                 : "=r"(r[0]), "=r"(r[1]), "=r"(r[2]), "=r"(r[3]) : "r"(a));
}
static __device__ __forceinline__ void mma(float d[4], const uint32_t a[4],
                                           uint32_t b0, uint32_t b1) {
    asm volatile(
        "mma.sync.aligned.m16n8k16.row.col.f32.bf16.bf16.f32 "
        "{%0,%1,%2,%3}, {%4,%5,%6,%7}, {%8,%9}, {%0,%1,%2,%3};"
        : "+f"(d[0]), "+f"(d[1]), "+f"(d[2]), "+f"(d[3])
        : "r"(a[0]), "r"(a[1]), "r"(a[2]), "r"(a[3]), "r"(b0), "r"(b1));
}
// split float4 -> two bf16x2 hi + two lo
static __device__ __forceinline__ void split4(float4 v, uint32_t& h0, uint32_t& h1,
                                              uint32_t& l0, uint32_t& l1) {
    h0 = packb(v.x, v.y);
    h1 = packb(v.z, v.w);
    l0 = packb(v.x - __uint_as_float(h0 << 16), v.y - __uint_as_float(h0 & 0xffff0000u));
    l1 = packb(v.z - __uint_as_float(h1 << 16), v.w - __uint_as_float(h1 & 0xffff0000u));
}

__global__ __launch_bounds__(512, 1)
void lf_hmma_kernel(const float* __restrict__ Q, const float* __restrict__ K,
                    const float* __restrict__ V, const float* __restrict__ AM,
                    float* __restrict__ O, int S) {
    extern __shared__ char sm[];
    const uint32_t sb = smem_u32(sm);
    const int tid  = threadIdx.x;
    const int w    = tid >> 5;
    const int lane = tid & 31;
    const int g    = lane >> 2;
    const int tg   = lane & 3;
    const int rg   = w >> 1;          // 16-row group 0..7
    const int cp   = w & 1;           // column parity within pair
    const int h    = blockIdx.y;
    const int q0   = blockIdx.x << 7;
    const int kb   = q0 - 128;
    const bool blk0 = (q0 == 0);

    const float* Qg = Q + ((size_t)h * S + q0) * 64;
    const float* Kg = K + (size_t)h * S * 64;
    const float* Vg = V + (size_t)h * S * 64;

    // ---- stage Q/K/V (bf16 hi/lo split) + mask into smem ----
#pragma unroll
    for (int it = 0; it < 4; ++it) {
        int idx = it * 512 + tid, row = idx >> 4, c4 = idx & 15;
        float4 q = *reinterpret_cast<const float4*>(Qg + row * 64 + c4 * 4);
        uint32_t h0, h1, l0, l1; split4(q, h0, h1, l0, l1);
        uint32_t off = (uint32_t)row * QP + (uint32_t)c4 * 8u;
        *reinterpret_cast<uint2*>(sm + QHI + off) = make_uint2(h0, h1);
        *reinterpret_cast<uint2*>(sm + QLO + off) = make_uint2(l0, l1);
    }
#pragma unroll
    for (int it = 0; it < 8; ++it) {
        int idx = it * 512 + tid, y = idx >> 4, c4 = idx & 15;
        float4 kv = make_float4(0.f,0.f,0.f,0.f), vv = make_float4(0.f,0.f,0.f,0.f);
        if (!blk0 || y >= 128) {
            kv = *reinterpret_cast<const float4*>(Kg + (size_t)(kb + y) * 64 + c4 * 4);
            vv = *reinterpret_cast<const float4*>(Vg + (size_t)(kb + y) * 64 + c4 * 4);
        }
        uint32_t off = (uint32_t)y * KP + (uint32_t)c4 * 8u;
        uint32_t h0, h1, l0, l1;
        split4(kv, h0, h1, l0, l1);
        *reinterpret_cast<uint2*>(sm + KHI + off) = make_uint2(h0, h1);
        *reinterpret_cast<uint2*>(sm + KLO + off) = make_uint2(l0, l1);
        split4(vv, h0, h1, l0, l1);
        *reinterpret_cast<uint2*>(sm + VHI + off) = make_uint2(h0, h1);
        *reinterpret_cast<uint2*>(sm + VLO + off) = make_uint2(l0, l1);
    }
    if (tid < 256) {
        float am = 0.f;
        if (!blk0 || tid >= 128) am = AM[kb + tid];
        reinterpret_cast<float*>(sm + AMS)[tid] = am;
    }
    __syncthreads();

    // ---- A fragments for Q (4 k-steps, hi+lo) ----
    uint32_t aqh[4][4], aql[4][4];
    {
        uint32_t ab = sb + QHI + (uint32_t)(rg * 16 + (lane & 15)) * QP +
                      (uint32_t)((lane >> 4) & 1) * 16u;
#pragma unroll
        for (int ks = 0; ks < 4; ++ks) {
            ldsm4(aqh[ks], ab + ks * 32);
            ldsm4(aql[ks], ab + (QLO - QHI) + ks * 32);
        }
    }

    const int ps = blk0 ? 8 : 0;      // first active pair
    const int pe = 9 + rg;            // exclusive pair bound (causal)

    union { float s[16][4]; uint32_t u[16][4]; } P;

    const uint32_t kb_h = sb + KHI + (uint32_t)(lane & 7) * KP +
                          (uint32_t)((lane >> 3) & 3) * 16u;

    // ---- Phase A: S = Q K^T (3-product bf16 split), this warp's parity ----
#pragma unroll
    for (int k = 0; k < 8; ++k) {
        const int p = 2 * k + cp;
        if (p < ps || p >= pe) continue;
#pragma unroll
        for (int t = 0; t < 2; ++t) {
            const int nt = 2 * p + t;
            float d0[4] = {0,0,0,0}, d1[4] = {0,0,0,0};
#pragma unroll
            for (int ph = 0; ph < 2; ++ph) {
                uint32_t bh[4], bl[4];
                ldsm4(bh, kb_h + (uint32_t)nt * 8u * KP + ph * 64);
                ldsm4(bl, kb_h + (KLO - KHI) + (uint32_t)nt * 8u * KP + ph * 64);
                const int k0 = 2 * ph, k1 = 2 * ph + 1;
                mma(d0, aqh[k0], bh[0], bh[1]);
                mma(d0, aqh[k1], bh[2], bh[3]);
                mma(d1, aqh[k0], bl[0], bl[1]);
                mma(d1, aqh[k1], bl[2], bl[3]);
                mma(d0, aql[k0], bh[0], bh[1]);
                mma(d0, aql[k1], bh[2], bh[3]);
            }
#pragma unroll
            for (int i = 0; i < 4; ++i) P.s[2*k + t][i] = d0[i] + d1[i];
        }
    }

    // ---- softmax rows r0, r0+8 (causal + additive mask, cross-warp pair) ----
    const int r0 = rg * 16 + g;
    const int lim0 = 128 + r0, lim1 = lim0 + 8;
    const float* AMsm = reinterpret_cast<const float*>(sm + AMS);
    float* redm = reinterpret_cast<float*>(sm + REDM);
    float* reds = reinterpret_cast<float*>(sm + REDS);

    float m0 = -1e30f, m1 = -1e30f;
#pragma unroll
    for (int k = 0; k < 8; ++k) {
        const int p = 2 * k + cp;
        if (p < ps || p >= pe) continue;
#pragma unroll
        for (int t = 0; t < 2; ++t) {
            const int nt = 2 * p + t;
            int col0 = nt * 8 + 2 * tg, col1 = col0 + 1;
            float am0 = AMsm[col0], am1 = AMsm[col1];
            float v0 = (col0 <= lim0) ? P.s[2*k+t][0] + am0 : -1e30f;
            float v1 = (col1 <= lim0) ? P.s[2*k+t][1] + am1 : -1e30f;
            float v2 = (col0 <= lim1) ? P.s[2*k+t][2] + am0 : -1e30f;
            float v3 = (col1 <= lim1) ? P.s[2*k+t][3] + am1 : -1e30f;
            P.s[2*k+t][0] = v0; P.s[2*k+t][1] = v1;
            P.s[2*k+t][2] = v2; P.s[2*k+t][3] = v3;
            m0 = fmaxf(m0, fmaxf(v0, v1));
            m1 = fmaxf(m1, fmaxf(v2, v3));
        }
    }
    m0 = fmaxf(m0, __shfl_xor_sync(0xffffffffu, m0, 1));
    m0 = fmaxf(m0, __shfl_xor_sync(0xffffffffu, m0, 2));
    m1 = fmaxf(m1, __shfl_xor_sync(0xffffffffu, m1, 1));
    m1 = fmaxf(m1, __shfl_xor_sync(0xffffffffu, m1, 2));
    if (tg == 0) {
        redm[cp * 128 + r0]     = m0;
        redm[cp * 128 + r0 + 8] = m1;
    }
    __syncthreads();
    m0 = fmaxf(m0, redm[(1 - cp) * 128 + r0]);
    m1 = fmaxf(m1, redm[(1 - cp) * 128 + r0 + 8]);

    float s0 = 0.f, s1 = 0.f;
#pragma unroll
    for (int k = 0; k < 8; ++k) {
        const int p = 2 * k + cp;
        if (p < ps || p >= pe) continue;
#pragma unroll
        for (int t = 0; t < 2; ++t) {
            float e0 = __expf(P.s[2*k+t][0] - m0);
            float e1 = __expf(P.s[2*k+t][1] - m0);
            float e2 = __expf(P.s[2*k+t][2] - m1);
            float e3 = __expf(P.s[2*k+t][3] - m1);
            P.s[2*k+t][0] = e0; P.s[2*k+t][1] = e1;
            P.s[2*k+t][2] = e2; P.s[2*k+t][3] = e3;
            s0 += e0 + e1; s1 += e2 + e3;
        }
    }
    s0 += __shfl_xor_sync(0xffffffffu, s0, 1);
    s0 += __shfl_xor_sync(0xffffffffu, s0, 2);
    s1 += __shfl_xor_sync(0xffffffffu, s1, 1);
    s1 += __shfl_xor_sync(0xffffffffu, s1, 2);
    if (tg == 0) {
        reds[cp * 128 + r0]     = s0;
        reds[cp * 128 + r0 + 8] = s1;
    }
    __syncthreads();
    s0 += reds[(1 - cp) * 128 + r0];
    s1 += reds[(1 - cp) * 128 + r0 + 8];
    const float inv0 = __frcp_rn(s0);
    const float inv1 = __frcp_rn(s1);

    // ---- normalize + split P to bf16 hi/lo in place ----
#pragma unroll
    for (int k = 0; k < 8; ++k) {
        const int p = 2 * k + cp;
        if (p < ps || p >= pe) continue;
#pragma unroll
        for (int t = 0; t < 2; ++t) {
            float p0 = P.s[2*k+t][0] * inv0, p1 = P.s[2*k+t][1] * inv0;
            float p2 = P.s[2*k+t][2] * inv1, p3 = P.s[2*k+t][3] * inv1;
            uint32_t h01 = packb(p0, p1);
            uint32_t h23 = packb(p2, p3);
            uint32_t l01 = packb(p0 - __uint_as_float(h01 << 16),
                                 p1 - __uint_as_float(h01 & 0xffff0000u));
            uint32_t l23 = packb(p2 - __uint_as_float(h23 << 16),
                                 p3 - __uint_as_float(h23 & 0xffff0000u));
            P.u[2*k+t][0] = h01; P.u[2*k+t][1] = h23;
            P.u[2*k+t][2] = l01; P.u[2*k+t][3] = l23;
        }
    }

    // ---- Phase B: partial O = P V over this warp's k-tiles ----
    float o[8][4];
#pragma unroll
    for (int i = 0; i < 8; ++i) { o[i][0] = o[i][1] = o[i][2] = o[i][3] = 0.f; }

    const uint32_t vb_h = sb + VHI +
        (uint32_t)(((lane >> 3) & 1) * 8 + (lane & 7)) * VP +
        (uint32_t)((lane >> 4) & 1) * 16u;

#pragma unroll
    for (int k = 0; k < 8; ++k) {
        const int p = 2 * k + cp;
        if (p < ps || p >= pe) continue;
        uint32_t ah[4] = {P.u[2*k][0], P.u[2*k][1], P.u[2*k+1][0], P.u[2*k+1][1]};
        uint32_t al[4] = {P.u[2*k][2], P.u[2*k][3], P.u[2*k+1][2], P.u[2*k+1][3]};
#pragma unroll
        for (int dp = 0; dp < 4; ++dp) {
            uint32_t bh[4], bl[4];
            ldsm4t(bh, vb_h + (uint32_t)p * 16u * VP + dp * 32);
            ldsm4t(bl, vb_h + (VLO - VHI) + (uint32_t)p * 16u * VP + dp * 32);
            mma(o[2*dp],     ah, bh[0], bh[1]);
            mma(o[2*dp + 1], ah, bh[2], bh[3]);
            mma(o[2*dp],     ah, bl[0], bl[1]);
            mma(o[2*dp + 1], ah, bl[2], bl[3]);
            mma(o[2*dp],     al, bh[0], bh[1]);
            mma(o[2*dp + 1], al, bh[2], bh[3]);
        }
    }

    // ---- cross-warp O reduction (cp=1 -> smem, cp=0 adds + stores) ----
    float4* oex = reinterpret_cast<float4*>(sm + OEX + (uint32_t)rg * 4096u);
    if (cp == 1) {
#pragma unroll
        for (int j = 0; j < 8; ++j)
            oex[j * 32 + lane] = make_float4(o[j][0], o[j][1], o[j][2], o[j][3]);
    }
    __syncthreads();
    if (cp == 0) {
        float* Ob = O + ((size_t)h * S + q0 + r0) * 64;
#pragma unroll
        for (int j = 0; j < 8; ++j) {
            float4 t = oex[j * 32 + lane];
            int d = j * 8 + 2 * tg;
            *reinterpret_cast<float2*>(Ob + d) =
                make_float2(o[j][0] + t.x, o[j][1] + t.y);
            *reinterpret_cast<float2*>(Ob + 8 * 64 + d) =
                make_float2(o[j][2] + t.z, o[j][3] + t.w);
        }
    }
}

extern "C" void kernel_launch(void* const* d_in, const int* in_sizes, int n_in,
                              void* d_out, int out_size) {
    const float* Q  = (const float*)d_in[0];
    const float* K  = (const float*)d_in[1];
    const float* V  = (const float*)d_in[2];
    const float* AM = (const float*)d_in[3];
    float* O = (float*)d_out;

    const int S  = in_sizes[3];
    const int BH = in_sizes[0] / (S * 64);

    cudaFuncSetAttribute(lf_hmma_kernel,
                         cudaFuncAttributeMaxDynamicSharedMemorySize, SMEM_TOTAL);

    dim3 grid(S / 128, BH);
    lf_hmma_kernel<<<grid, 512, SMEM_TOTAL>>>(Q, K, V, AM, O, S);
}

// round 5
// speedup vs baseline: 1.4689x; 1.4689x over previous
#include <cuda_runtime.h>
#include <cuda_fp16.h>
#include <cstdint>

// ---------------------------------------------------------------------------
// Banded causal attention (Longformer w=128, window 256, D=64) on mma.sync
// fp16 HMMA. QK: 3-product hi/lo split (fp32-grade scores). PV: 2 products
// (P single fp16, V hi+lo). CTA = 128 q-rows, 8 warps, 1 CTA/SM.
// ---------------------------------------------------------------------------

#define QP 144u
#define KP 144u
#define VP 144u
#define QHI 0u
#define QLO 18432u
#define KHI 36864u
#define KLO 73728u
#define VHI 110592u
#define VLO 147456u
#define AMS 184320u
#define SMEM_TOTAL 185344

#define LOG2E 1.4426950408889634f

static __device__ __forceinline__ uint32_t smem_u32(const void* p) {
    uint32_t a;
    asm("{ .reg .u64 t; cvta.to.shared.u64 t, %1; cvt.u32.u64 %0, t; }"
        : "=r"(a) : "l"(p));
    return a;
}
// pack two f32 -> f16x2 (first arg in low half)
static __device__ __forceinline__ uint32_t packh(float lo, float hi) {
    uint32_t r;
    asm("cvt.rn.f16x2.f32 %0, %1, %2;" : "=r"(r) : "f"(hi), "f"(lo));
    return r;
}
static __device__ __forceinline__ float lowf(uint32_t u) {
    return __half2float(__ushort_as_half((unsigned short)(u & 0xffffu)));
}
static __device__ __forceinline__ float highf(uint32_t u) {
    return __half2float(__ushort_as_half((unsigned short)(u >> 16)));
}
static __device__ __forceinline__ void ldsm4(uint32_t r[4], uint32_t a) {
    asm volatile("ldmatrix.sync.aligned.m8n8.x4.shared.b16 {%0,%1,%2,%3}, [%4];"
                 : "=r"(r[0]), "=r"(r[1]), "=r"(r[2]), "=r"(r[3]) : "r"(a));
}
static __device__ __forceinline__ void ldsm4t(uint32_t r[4], uint32_t a) {
    asm volatile("ldmatrix.sync.aligned.m8n8.x4.trans.shared.b16 {%0,%1,%2,%3}, [%4];"
                 : "=r"(r[0]), "=r"(r[1]), "=r"(r[2]), "=r"(r[3]) : "r"(a));
}
static __device__ __forceinline__ void mma(float d[4], const uint32_t a[4],
                                           uint32_t b0, uint32_t b1) {
    asm volatile(
        "mma.sync.aligned.m16n8k16.row.col.f32.f16.f16.f32 "
        "{%0,%1,%2,%3}, {%4,%5,%6,%7}, {%8,%9}, {%0,%1,%2,%3};"
        : "+f"(d[0]), "+f"(d[1]), "+f"(d[2]), "+f"(d[3])
        : "r"(a[0]), "r"(a[1]), "r"(a[2]), "r"(a[3]), "r"(b0), "r"(b1));
}
// split float4 -> two f16x2 hi + two f16x2 lo
static __device__ __forceinline__ void split4(float4 v, uint32_t& h0, uint32_t& h1,
                                              uint32_t& l0, uint32_t& l1) {
    h0 = packh(v.x, v.y);
    h1 = packh(v.z, v.w);
    l0 = packh(v.x - lowf(h0), v.y - highf(h0));
    l1 = packh(v.z - lowf(h1), v.w - highf(h1));
}

__global__ __launch_bounds__(256)
void lf_hmma_kernel(const float* __restrict__ Q, const float* __restrict__ K,
                    const float* __restrict__ V, const float* __restrict__ AM,
                    float* __restrict__ O, int S) {
    extern __shared__ char sm[];
    const uint32_t sb = smem_u32(sm);
    const int tid  = threadIdx.x;
    const int w    = tid >> 5;
    const int lane = tid & 31;
    const int g    = lane >> 2;
    const int tg   = lane & 3;
    const int h    = blockIdx.y;
    const int q0   = blockIdx.x << 7;
    const int kb   = q0 - 128;
    const bool blk0 = (q0 == 0);

    const float* Qg = Q + ((size_t)h * S + q0) * 64;
    const float* Kg = K + (size_t)h * S * 64;
    const float* Vg = V + (size_t)h * S * 64;

    // ---- stage Q/K/V (fp16 hi/lo split) + mask(*log2e) into smem ----
#pragma unroll
    for (int it = 0; it < 8; ++it) {
        int idx = it * 256 + tid, row = idx >> 4, c4 = idx & 15;
        float4 q = *reinterpret_cast<const float4*>(Qg + row * 64 + c4 * 4);
        uint32_t h0, h1, l0, l1; split4(q, h0, h1, l0, l1);
        uint32_t off = (uint32_t)row * QP + (uint32_t)c4 * 8u;
        *reinterpret_cast<uint2*>(sm + QHI + off) = make_uint2(h0, h1);
        *reinterpret_cast<uint2*>(sm + QLO + off) = make_uint2(l0, l1);
    }
#pragma unroll
    for (int it = 0; it < 16; ++it) {
        int idx = it * 256 + tid, y = idx >> 4, c4 = idx & 15;
        float4 kv = make_float4(0.f,0.f,0.f,0.f), vv = make_float4(0.f,0.f,0.f,0.f);
        if (!blk0 || y >= 128) {
            kv = *reinterpret_cast<const float4*>(Kg + (size_t)(kb + y) * 64 + c4 * 4);
            vv = *reinterpret_cast<const float4*>(Vg + (size_t)(kb + y) * 64 + c4 * 4);
        }
        uint32_t off = (uint32_t)y * KP + (uint32_t)c4 * 8u;
        uint32_t h0, h1, l0, l1;
        split4(kv, h0, h1, l0, l1);
        *reinterpret_cast<uint2*>(sm + KHI + off) = make_uint2(h0, h1);
        *reinterpret_cast<uint2*>(sm + KLO + off) = make_uint2(l0, l1);
        split4(vv, h0, h1, l0, l1);
        *reinterpret_cast<uint2*>(sm + VHI + off) = make_uint2(h0, h1);
        *reinterpret_cast<uint2*>(sm + VLO + off) = make_uint2(l0, l1);
    }
    {
        float am = 0.f;
        if (!blk0 || tid >= 128) am = AM[kb + tid] * LOG2E;
        reinterpret_cast<float*>(sm + AMS)[tid] = am;
    }
    __syncthreads();

    // ---- A fragments for Q (4 k-steps, hi+lo) ----
    uint32_t aqh[4][4], aql[4][4];
    {
        uint32_t ab = sb + QHI + (uint32_t)(w * 16 + (lane & 15)) * QP +
                      (uint32_t)((lane >> 4) & 1) * 16u;
#pragma unroll
        for (int ks = 0; ks < 4; ++ks) {
            ldsm4(aqh[ks], ab + ks * 32);
            ldsm4(aql[ks], ab + (QLO - QHI) + ks * 32);
        }
    }

    const int ns = blk0 ? 16 : 0;
    const int ne = 18 + 2 * w;   // exclusive n-tile bound (causal)

    union { float s[32][4]; uint32_t u[32][4]; } P;

    const uint32_t kb_h = sb + KHI + (uint32_t)(lane & 7) * KP +
                          (uint32_t)((lane >> 3) & 3) * 16u;
    const uint32_t kb_l = kb_h + (KLO - KHI);

    // ---- Phase A: S = Q K^T (3-product fp16 split) ----
#pragma unroll
    for (int nt = 0; nt < 32; nt += 2) {
        if (nt < ns || nt >= ne) continue;
        float dA0[4] = {0,0,0,0}, dB0[4] = {0,0,0,0};
        float dA1[4] = {0,0,0,0}, dB1[4] = {0,0,0,0};
#pragma unroll
        for (int p = 0; p < 2; ++p) {
            uint32_t bh[4], bl[4], ch[4], cl[4];
            ldsm4(bh, kb_h + (uint32_t)nt * 8u * KP + p * 64);
            ldsm4(bl, kb_l + (uint32_t)nt * 8u * KP + p * 64);
            ldsm4(ch, kb_h + (uint32_t)(nt + 1) * 8u * KP + p * 64);
            ldsm4(cl, kb_l + (uint32_t)(nt + 1) * 8u * KP + p * 64);
            const int k0 = 2 * p, k1 = 2 * p + 1;
            mma(dA0, aqh[k0], bh[0], bh[1]);
            mma(dA1, aqh[k0], ch[0], ch[1]);
            mma(dB0, aqh[k0], bl[0], bl[1]);
            mma(dB1, aqh[k0], cl[0], cl[1]);
            mma(dA0, aqh[k1], bh[2], bh[3]);
            mma(dA1, aqh[k1], ch[2], ch[3]);
            mma(dB0, aqh[k1], bl[2], bl[3]);
            mma(dB1, aqh[k1], cl[2], cl[3]);
            if (p == 0) {
                mma(dA0, aql[k0], bh[0], bh[1]);
                mma(dA1, aql[k0], ch[0], ch[1]);
                mma(dA0, aql[k1], bh[2], bh[3]);
                mma(dA1, aql[k1], ch[2], ch[3]);
            } else {
                mma(dB0, aql[k0], bh[0], bh[1]);
                mma(dB1, aql[k0], ch[0], ch[1]);
                mma(dB0, aql[k1], bh[2], bh[3]);
                mma(dB1, aql[k1], ch[2], ch[3]);
            }
        }
#pragma unroll
        for (int i = 0; i < 4; ++i) {
            P.s[nt][i]     = dA0[i] + dB0[i];
            P.s[nt + 1][i] = dA1[i] + dB1[i];
        }
    }

    // ---- softmax in base-2 (scores scaled by log2e during mask fold) ----
    const int r0 = w * 16 + g;
    const int lim0 = 128 + r0, lim1 = lim0 + 8;
    const float* AMsm = reinterpret_cast<const float*>(sm + AMS);

    float m0 = -1e30f, m1 = -1e30f;
#pragma unroll
    for (int nt = 0; nt < 32; ++nt) {
        if (nt < ns || nt >= ne) continue;
        int col0 = nt * 8 + 2 * tg, col1 = col0 + 1;
        float am0 = AMsm[col0], am1 = AMsm[col1];
        float v0 = (col0 <= lim0) ? fmaf(P.s[nt][0], LOG2E, am0) : -1e30f;
        float v1 = (col1 <= lim0) ? fmaf(P.s[nt][1], LOG2E, am1) : -1e30f;
        float v2 = (col0 <= lim1) ? fmaf(P.s[nt][2], LOG2E, am0) : -1e30f;
        float v3 = (col1 <= lim1) ? fmaf(P.s[nt][3], LOG2E, am1) : -1e30f;
        P.s[nt][0] = v0; P.s[nt][1] = v1; P.s[nt][2] = v2; P.s[nt][3] = v3;
        m0 = fmaxf(m0, fmaxf(v0, v1));
        m1 = fmaxf(m1, fmaxf(v2, v3));
    }
    m0 = fmaxf(m0, __shfl_xor_sync(0xffffffffu, m0, 1));
    m0 = fmaxf(m0, __shfl_xor_sync(0xffffffffu, m0, 2));
    m1 = fmaxf(m1, __shfl_xor_sync(0xffffffffu, m1, 1));
    m1 = fmaxf(m1, __shfl_xor_sync(0xffffffffu, m1, 2));

    float s0 = 0.f, s1 = 0.f;
#pragma unroll
    for (int nt = 0; nt < 32; ++nt) {
        if (nt < ns || nt >= ne) continue;
        float e0 = exp2f(P.s[nt][0] - m0);
        float e1 = exp2f(P.s[nt][1] - m0);
        float e2 = exp2f(P.s[nt][2] - m1);
        float e3 = exp2f(P.s[nt][3] - m1);
        P.s[nt][0] = e0; P.s[nt][1] = e1; P.s[nt][2] = e2; P.s[nt][3] = e3;
        s0 += e0 + e1; s1 += e2 + e3;
    }
    s0 += __shfl_xor_sync(0xffffffffu, s0, 1);
    s0 += __shfl_xor_sync(0xffffffffu, s0, 2);
    s1 += __shfl_xor_sync(0xffffffffu, s1, 1);
    s1 += __shfl_xor_sync(0xffffffffu, s1, 2);
    const float inv0 = __frcp_rn(s0);
    const float inv1 = __frcp_rn(s1);

    // ---- normalize + pack P to single fp16 (no lo plane needed) ----
    // u[nt][0] = f16x2 rows (g, cols c0,c1), u[nt][1] = rows (g+8)
#pragma unroll
    for (int nt = 0; nt < 32; ++nt) {
        if (nt < ns || nt >= ne) continue;
        float p0 = P.s[nt][0] * inv0, p1 = P.s[nt][1] * inv0;
        float p2 = P.s[nt][2] * inv1, p3 = P.s[nt][3] * inv1;
        P.u[nt][0] = packh(p0, p1);
        P.u[nt][1] = packh(p2, p3);
    }

    // ---- Phase B: O = P V (2 products: Phi*Vhi + Phi*Vlo) ----
    float o[8][4];
#pragma unroll
    for (int i = 0; i < 8; ++i) { o[i][0] = o[i][1] = o[i][2] = o[i][3] = 0.f; }

    const uint32_t vb_h = sb + VHI +
        (uint32_t)(((lane >> 3) & 1) * 8 + (lane & 7)) * VP +
        (uint32_t)((lane >> 4) & 1) * 16u;
    const uint32_t vb_l = vb_h + (VLO - VHI);
    const int ktlo = ns >> 1, kthi = ne >> 1;

#pragma unroll
    for (int kt = 0; kt < 16; ++kt) {
        if (kt < ktlo || kt >= kthi) continue;
        uint32_t ah[4] = {P.u[2*kt][0], P.u[2*kt][1], P.u[2*kt+1][0], P.u[2*kt+1][1]};
#pragma unroll
        for (int dp = 0; dp < 4; ++dp) {
            uint32_t bh[4], bl[4];
            ldsm4t(bh, vb_h + (uint32_t)kt * 16u * VP + dp * 32);
            ldsm4t(bl, vb_l + (uint32_t)kt * 16u * VP + dp * 32);
            mma(o[2*dp],     ah, bh[0], bh[1]);
            mma(o[2*dp + 1], ah, bh[2], bh[3]);
            mma(o[2*dp],     ah, bl[0], bl[1]);
            mma(o[2*dp + 1], ah, bl[2], bl[3]);
        }
    }

    // ---- store O ----
    float* Ob = O + ((size_t)h * S + q0 + r0) * 64;
#pragma unroll
    for (int dp = 0; dp < 8; ++dp) {
        int d = dp * 8 + 2 * tg;
        *reinterpret_cast<float2*>(Ob + d)           = make_float2(o[dp][0], o[dp][1]);
        *reinterpret_cast<float2*>(Ob + 8 * 64 + d)  = make_float2(o[dp][2], o[dp][3]);
    }
}

extern "C" void kernel_launch(void* const* d_in, const int* in_sizes, int n_in,
                              void* d_out, int out_size) {
    const float* Q  = (const float*)d_in[0];
    const float* K  = (const float*)d_in[1];
    const float* V  = (const float*)d_in[2];
    const float* AM = (const float*)d_in[3];
    float* O = (float*)d_out;

    const int S  = in_sizes[3];
    const int BH = in_sizes[0] / (S * 64);

    cudaFuncSetAttribute(lf_hmma_kernel,
                         cudaFuncAttributeMaxDynamicSharedMemorySize, SMEM_TOTAL);

    dim3 grid(S / 128, BH);
    lf_hmma_kernel<<<grid, 256, SMEM_TOTAL>>>(Q, K, V, AM, O, S);
}